// round 11
// baseline (speedup 1.0000x reference)
#include <cuda_runtime.h>
#include <cstdint>

// QNADE — autoregressive NADE. N=8192, D=64, H=4096, M=2.
// R10 skeleton + W2 moved to REGISTERS (site-invariant) to kill the dominant
// LDS crossbar stream (12B -> 4B per element).
//   1 CTA = 1 sample, 256 threads, PER_THR=16.
//   acc pre-scaled: acc = 2*log2(e)*(b1 + sum_j x_j W1[j,:])
//   q = 1/(exp2(acc)+1) (tanh = 1-2q), 4-way shared rcp
//   z = C - 2*dot(q, W2col), C = sum(W2col)+b2 (once)

#define N_SAMP   8192
#define D_SITES  64
#define H_DIM    4096
#define THREADS  256
#define PER_THR  16           // h-elements per thread
#define PAD_CH   20           // 16 data + 4 pad words -> conflict-free LDS.128
#define CH       (THREADS * PAD_CH)   // 5120 floats per W1 row buffer
#define KTANH    2.8853900817779268f  // 2*log2(e)

typedef unsigned long long ull;

__device__ __forceinline__ ull pk(float a, float b) {
    ull r; asm("mov.b64 %0, {%1, %2};" : "=l"(r) : "f"(a), "f"(b)); return r;
}
__device__ __forceinline__ void upk(ull v, float& a, float& b) {
    asm("mov.b64 {%0, %1}, %2;" : "=f"(a), "=f"(b) : "l"(v));
}
__device__ __forceinline__ ull fma2(ull a, ull b, ull c) {
    ull d; asm("fma.rn.f32x2 %0, %1, %2, %3;" : "=l"(d) : "l"(a), "l"(b), "l"(c)); return d;
}
__device__ __forceinline__ float fex2(float x) {
    float e; asm("ex2.approx.f32 %0, %1;" : "=f"(e) : "f"(x)); return e;
}
__device__ __forceinline__ float frcp(float x) {
    float r; asm("rcp.approx.f32 %0, %1;" : "=f"(r) : "f"(x)); return r;
}
__device__ __forceinline__ void cp16(uint32_t dst, const void* src) {
    asm volatile("cp.async.ca.shared.global [%0], [%1], 16;" :: "r"(dst), "l"(src));
}

// 4 elements: q_i = 1/(exp2(acc_i)+1) with ONE rcp; dot q (vs reg-resident W2)
// into d0v/d1v; then acc += xv*w1 (q uses pre-update acc: site-d ordering).
__device__ __forceinline__ void process4(ull& a0, ull& a1,
                                         ull w1x, ull w1y,
                                         ull wxx, ull wxy,
                                         ull wyx, ull wyy,
                                         ull xv, ull& d0v, ull& d1v) {
    float s0, s1, s2, s3;
    upk(a0, s0, s1); upk(a1, s2, s3);
    const float e0 = fex2(s0), e1 = fex2(s1), e2 = fex2(s2), e3 = fex2(s3);
    const float u0 = e0 + 1.0f, u1 = e1 + 1.0f, u2 = e2 + 1.0f, u3 = e3 + 1.0f;
    const float b = u0 * u1;
    const float c = b * u2;
    const float p = c * u3;
    const float r  = frcp(p);
    const float q3 = r * c;
    const float r3 = r * u3;
    const float q2 = r3 * b;
    const float r2 = r3 * u2;          // 1/(u0*u1)
    const float q1 = r2 * u0;
    const float q0 = r2 * u1;
    const ull qv0 = pk(q0, q1);
    const ull qv1 = pk(q2, q3);
    d0v = fma2(qv0, wxx, d0v);  d0v = fma2(qv1, wxy, d0v);
    d1v = fma2(qv0, wyx, d1v);  d1v = fma2(qv1, wyy, d1v);
    a0 = fma2(xv, w1x, a0);
    a1 = fma2(xv, w1y, a1);
}

__global__ __launch_bounds__(THREADS, 3)
void qnade_kernel(const float* __restrict__ x,
                  const float* __restrict__ W1,
                  const float* __restrict__ b1,
                  const float* __restrict__ W2,
                  const float* __restrict__ b2,
                  float* __restrict__ out)
{
    // smem (floats): W1s[2][CH] | Xs[64] | red[2][8] float2
    extern __shared__ float smem[];
    float*  W1s = smem;                      // 2*5120
    float*  Xs  = smem + 2 * CH;             // 64
    float2* red = (float2*)(Xs + D_SITES);   // 16 float2

    const int t    = threadIdx.x;            // == h-chunk 0..255
    const int warp = t >> 5;
    const int lane = t & 31;
    const int n    = blockIdx.x;             // sample
    const bool leader = (t == 0);
    const uint32_t smem_u32 = (uint32_t)__cvta_generic_to_shared(smem);

    // ---- stage spins (one sample) ----
    if (t < D_SITES) Xs[t] = x[(size_t)n * D_SITES + t];

    // ---- stage W1 row 0 into buffer 0 (1024 granules, 4/thread) ----
    #pragma unroll
    for (int j = t; j < H_DIM / 4; j += THREADS)
        cp16(smem_u32 + (uint32_t)((j >> 2) * PAD_CH + ((j & 3) << 2)) * 4u, W1 + 4 * j);
    asm volatile("cp.async.commit_group;");

    // ---- W2 into registers (site-invariant): 8 packed wx + 8 packed wy ----
    ull wxp[8], wyp[8];
    {
        const float2* W2g = (const float2*)W2;   // W2 is [H,2] row-major
        #pragma unroll
        for (int k = 0; k < 8; k++) {
            const float2 a = W2g[t * PER_THR + 2 * k];
            const float2 b = W2g[t * PER_THR + 2 * k + 1];
            wxp[k] = pk(a.x, b.x);
            wyp[k] = pk(a.y, b.y);
        }
    }

    // ---- acc init: pre-scaled b1 ----
    ull acc[8];
    {
        const float4* b1v = (const float4*)(b1 + t * PER_THR);
        #pragma unroll
        for (int k = 0; k < 4; k++) {
            const float4 v = b1v[k];
            acc[2 * k]     = pk(KTANH * v.x, KTANH * v.y);
            acc[2 * k + 1] = pk(KTANH * v.z, KTANH * v.w);
        }
    }

    // ---- one-time C0/C1 = sum(W2 col) + b2 (from registers) ----
    float C0 = 0.0f, C1 = 0.0f;
    {
        float sx = 0.0f, sy = 0.0f;
        #pragma unroll
        for (int k = 0; k < 8; k++) {
            float a, b;
            upk(wxp[k], a, b); sx += a + b;
            upk(wyp[k], a, b); sy += a + b;
        }
        #pragma unroll
        for (int o = 16; o; o >>= 1) {
            sx += __shfl_xor_sync(0xffffffffu, sx, o);
            sy += __shfl_xor_sync(0xffffffffu, sy, o);
        }
        asm volatile("cp.async.wait_group 0;" ::: "memory");
        if (lane == 0) red[8 + warp] = make_float2(sx, sy);
        __syncthreads();   // also publishes Xs + W1 row 0
        if (leader) {
            float a0s = 0.0f, a1s = 0.0f;
            #pragma unroll
            for (int w = 0; w < 8; w++) {
                const float2 v = red[8 + w];
                a0s += v.x; a1s += v.y;
            }
            C0 = a0s + b2[0];
            C1 = a1s + b2[1];
        }
    }

    float wav = 1.0f;
    int buf = 0;

    for (int d = 0; d < D_SITES; d++) {
        // prefetch W1 row d+1 into the other buffer
        if (d + 1 < D_SITES) {
            const float* src = W1 + (size_t)(d + 1) * H_DIM;
            const uint32_t dbase = smem_u32 + (uint32_t)((buf ^ 1) * CH) * 4u;
            #pragma unroll
            for (int j = t; j < H_DIM / 4; j += THREADS)
                cp16(dbase + (uint32_t)((j >> 2) * PAD_CH + ((j & 3) << 2)) * 4u, src + 4 * j);
        }
        asm volatile("cp.async.commit_group;");

        const float xs = Xs[d];
        const float cx = KTANH * xs;
        const ull xv = pk(cx, cx);
        const float* W1b = W1s + buf * CH + t * PAD_CH;

        ull d0v = 0ull, d1v = 0ull;
        #pragma unroll
        for (int q = 0; q < 4; q++) {
            const ulonglong2 w1q = *(const ulonglong2*)(W1b + 4 * q);   // 4 floats
            process4(acc[2 * q], acc[2 * q + 1],
                     w1q.x, w1q.y,
                     wxp[2 * q], wxp[2 * q + 1],
                     wyp[2 * q], wyp[2 * q + 1],
                     xv, d0v, d1v);
        }
        float a, b;
        upk(d0v, a, b); float D0 = a + b;
        upk(d1v, a, b); float D1 = a + b;

        #pragma unroll
        for (int o = 16; o; o >>= 1) {
            D0 += __shfl_xor_sync(0xffffffffu, D0, o);
            D1 += __shfl_xor_sync(0xffffffffu, D1, o);
        }
        float2* redb = red + (d & 1) * 8;
        if (lane == 0) redb[warp] = make_float2(D0, D1);

        asm volatile("cp.async.wait_group 0;" ::: "memory");
        __syncthreads();   // publishes red AND next W1 buffer

        if (leader) {
            float S0 = 0.0f, S1 = 0.0f;
            #pragma unroll
            for (int w = 0; w < 8; w++) {
                const float2 v = redb[w];
                S0 += v.x; S1 += v.y;
            }
            const float z0 = fmaf(-2.0f, S0, C0);
            const float z1 = fmaf(-2.0f, S1, C1);
            const float t0 = tanhf(z0), t1 = tanhf(z1);
            const float nrm = fmaxf(sqrtf(t0 * t0 + t1 * t1), 1e-12f);
            wav *= (xs > 0.0f ? t0 : t1) / nrm;
        }
        buf ^= 1;
    }

    if (leader) out[n] = wav;
}

extern "C" void kernel_launch(void* const* d_in, const int* in_sizes, int n_in,
                              void* d_out, int out_size) {
    const float* x  = (const float*)d_in[0];   // [8192,64]
    const float* W1 = (const float*)d_in[1];   // [64,4096]
    const float* b1 = (const float*)d_in[2];   // [4096]
    const float* W2 = (const float*)d_in[3];   // [4096,2]
    const float* b2 = (const float*)d_in[4];   // [2]
    float* out = (float*)d_out;                // [8192]

    const int smem_bytes =
        (2 * CH + D_SITES) * (int)sizeof(float) + 16 * (int)sizeof(float2);

    cudaFuncSetAttribute(qnade_kernel,
                         cudaFuncAttributeMaxDynamicSharedMemorySize, smem_bytes);

    qnade_kernel<<<N_SAMP, THREADS, smem_bytes>>>(x, W1, b1, W2, b2, out);
}

// round 12
// speedup vs baseline: 1.2275x; 1.2275x over previous
#include <cuda_runtime.h>
#include <cstdint>

// QNADE — autoregressive NADE. N=8192, D=64, H=4096, M=2.
// R10 skeleton (best: 1175us) with FULLY SCALAR math: no 64-bit packing.
// Diagnosis: packed f32x2 path paid ~3 ALU inst/elem in pack/unpack + pair
// alignment MOVs (alu pipe 39% busy). Scalar trades +1.6 FMA/elem for -3 ALU.
//   acc pre-scaled: acc = 2*log2(e)*(b1 + sum_j x_j W1[j,:])
//   q = 1/(exp2(acc)+1)  (tanh = 1-2q), 4-way shared rcp
//   z = C - 2*dot(q, W2col), C = sum(W2col)+b2 (once)

#define N_SAMP   8192
#define D_SITES  64
#define H_DIM    4096
#define B_SAMP   4
#define THREADS  512
#define HPART    128          // threads per sample
#define PER_THR  32           // h-elements per thread
#define PAD_CH   36           // 32 data + 4 pad words -> conflict-free LDS.128
#define CH       (HPART * PAD_CH)    // 4608 floats per W1 row buffer
#define KTANH    2.8853900817779268f // 2*log2(e)

__device__ __forceinline__ float fex2(float x) {
    float e; asm("ex2.approx.f32 %0, %1;" : "=f"(e) : "f"(x)); return e;
}
__device__ __forceinline__ float frcp(float x) {
    float r; asm("rcp.approx.f32 %0, %1;" : "=f"(r) : "f"(x)); return r;
}
__device__ __forceinline__ void cp16(uint32_t dst, const void* src) {
    asm volatile("cp.async.ca.shared.global [%0], [%1], 16;" :: "r"(dst), "l"(src));
}

__global__ __launch_bounds__(THREADS, 2)
void qnade_kernel(const float* __restrict__ x,
                  const float* __restrict__ W1,
                  const float* __restrict__ b1,
                  const float* __restrict__ W2,
                  const float* __restrict__ b2,
                  float* __restrict__ out)
{
    // smem (floats): W1s[2][CH] | W2xs[CH] | W2ys[CH] | Xs[256] | red[2][16] float2
    extern __shared__ float smem[];
    float*  W1s  = smem;
    float*  W2xs = smem + 2 * CH;
    float*  W2ys = W2xs + CH;
    float*  Xs   = W2ys + CH;
    float2* red  = (float2*)(Xs + B_SAMP * D_SITES);

    const int t    = threadIdx.x;
    const int nl   = t >> 7;        // local sample 0..3
    const int hp   = t & 127;       // h-chunk 0..127 (32 h-values each)
    const int warp = t >> 5;
    const int lane = t & 31;
    const int n0   = blockIdx.x * B_SAMP;
    const bool leader = (hp == 0);
    const uint32_t smem_u32 = (uint32_t)__cvta_generic_to_shared(smem);

    // ---- stage W2 (split, chunk-padded) + spins ----
    const float2* W2g = (const float2*)W2;
    #pragma unroll
    for (int i = t; i < H_DIM; i += THREADS) {
        const float2 g = W2g[i];
        const int c = i >> 5, k = i & 31;
        W2xs[c * PAD_CH + k] = g.x;
        W2ys[c * PAD_CH + k] = g.y;
    }
    if (t < B_SAMP * D_SITES)
        Xs[t] = x[(size_t)n0 * D_SITES + t];

    // ---- stage W1 row 0 into buffer 0 ----
    #pragma unroll
    for (int j = t; j < H_DIM / 4; j += THREADS)
        cp16(smem_u32 + (uint32_t)((j >> 3) * PAD_CH + ((j & 7) << 2)) * 4u, W1 + 4 * j);
    asm volatile("cp.async.commit_group;");

    // ---- acc init: pre-scaled b1 (plain floats) ----
    float acc[PER_THR];
    {
        const float4* b1v = (const float4*)(b1 + hp * PER_THR);
        #pragma unroll
        for (int k = 0; k < 8; k++) {
            const float4 v = b1v[k];
            acc[4 * k + 0] = KTANH * v.x;
            acc[4 * k + 1] = KTANH * v.y;
            acc[4 * k + 2] = KTANH * v.z;
            acc[4 * k + 3] = KTANH * v.w;
        }
    }

    asm volatile("cp.async.wait_group 0;" ::: "memory");
    __syncthreads();   // W2/Xs/W1row0 visible

    const float* WXb = W2xs + hp * PAD_CH;
    const float* WYb = W2ys + hp * PAD_CH;

    // ---- one-time C0/C1 = sum(W2 col) + b2 ----
    float C0 = 0.0f, C1 = 0.0f;
    {
        float sx = 0.0f, sy = 0.0f;
        const float4* wx4 = (const float4*)WXb;
        const float4* wy4 = (const float4*)WYb;
        #pragma unroll
        for (int k = 0; k < 8; k++) {
            const float4 a = wx4[k], bq = wy4[k];
            sx += (a.x + a.y) + (a.z + a.w);
            sy += (bq.x + bq.y) + (bq.z + bq.w);
        }
        #pragma unroll
        for (int o = 16; o; o >>= 1) {
            sx += __shfl_xor_sync(0xffffffffu, sx, o);
            sy += __shfl_xor_sync(0xffffffffu, sy, o);
        }
        if (lane == 0) red[warp] = make_float2(sx, sy);
        __syncthreads();
        if (leader) {
            float a0s = 0.0f, a1s = 0.0f;
            #pragma unroll
            for (int w = 0; w < 4; w++) {
                const float2 v = red[nl * 4 + w];
                a0s += v.x; a1s += v.y;
            }
            C0 = a0s + b2[0];
            C1 = a1s + b2[1];
        }
        __syncthreads();   // red free for the main loop
    }

    float wav = 1.0f;
    int buf = 0;

    for (int d = 0; d < D_SITES; d++) {
        // prefetch W1 row d+1 into the other buffer
        if (d + 1 < D_SITES) {
            const float* src = W1 + (size_t)(d + 1) * H_DIM;
            const uint32_t dbase = smem_u32 + (uint32_t)((buf ^ 1) * CH) * 4u;
            #pragma unroll
            for (int j = t; j < H_DIM / 4; j += THREADS)
                cp16(dbase + (uint32_t)((j >> 3) * PAD_CH + ((j & 7) << 2)) * 4u, src + 4 * j);
        }
        asm volatile("cp.async.commit_group;");

        const float xs = Xs[nl * D_SITES + d];
        const float cx = KTANH * xs;
        const float* W1b = W1s + buf * CH + hp * PAD_CH;

        // two accumulators per output column to shorten FFMA chains
        float d0a = 0.0f, d0b = 0.0f, d1a = 0.0f, d1b = 0.0f;

        #pragma unroll
        for (int q = 0; q < 8; q++) {
            const float4 w1 = *(const float4*)(W1b + 4 * q);
            const float4 wx = *(const float4*)(WXb + 4 * q);
            const float4 wy = *(const float4*)(WYb + 4 * q);
            const float s0 = acc[4 * q + 0];
            const float s1 = acc[4 * q + 1];
            const float s2 = acc[4 * q + 2];
            const float s3 = acc[4 * q + 3];
            const float u0 = fex2(s0) + 1.0f;
            const float u1 = fex2(s1) + 1.0f;
            const float u2 = fex2(s2) + 1.0f;
            const float u3 = fex2(s3) + 1.0f;
            const float b = u0 * u1;
            const float c = b * u2;
            const float p = c * u3;
            const float r  = frcp(p);
            const float q3 = r * c;
            const float r3 = r * u3;
            const float q2 = r3 * b;
            const float r2 = r3 * u2;      // 1/(u0*u1)
            const float q1 = r2 * u0;
            const float q0 = r2 * u1;
            d0a = fmaf(q0, wx.x, d0a);
            d0b = fmaf(q1, wx.y, d0b);
            d0a = fmaf(q2, wx.z, d0a);
            d0b = fmaf(q3, wx.w, d0b);
            d1a = fmaf(q0, wy.x, d1a);
            d1b = fmaf(q1, wy.y, d1b);
            d1a = fmaf(q2, wy.z, d1a);
            d1b = fmaf(q3, wy.w, d1b);
            acc[4 * q + 0] = fmaf(cx, w1.x, s0);
            acc[4 * q + 1] = fmaf(cx, w1.y, s1);
            acc[4 * q + 2] = fmaf(cx, w1.z, s2);
            acc[4 * q + 3] = fmaf(cx, w1.w, s3);
        }
        float D0 = d0a + d0b;
        float D1 = d1a + d1b;

        #pragma unroll
        for (int o = 16; o; o >>= 1) {
            D0 += __shfl_xor_sync(0xffffffffu, D0, o);
            D1 += __shfl_xor_sync(0xffffffffu, D1, o);
        }
        float2* redb = red + (d & 1) * 16;
        if (lane == 0) redb[warp] = make_float2(D0, D1);

        asm volatile("cp.async.wait_group 0;" ::: "memory");
        __syncthreads();   // publishes red AND next W1 buffer

        if (leader) {
            const float2 r0 = redb[nl * 4 + 0];
            const float2 r1 = redb[nl * 4 + 1];
            const float2 r2 = redb[nl * 4 + 2];
            const float2 r3 = redb[nl * 4 + 3];
            const float S0 = (r0.x + r1.x) + (r2.x + r3.x);
            const float S1 = (r0.y + r1.y) + (r2.y + r3.y);
            const float z0 = fmaf(-2.0f, S0, C0);
            const float z1 = fmaf(-2.0f, S1, C1);
            const float t0 = tanhf(z0), t1 = tanhf(z1);
            const float nrm = fmaxf(sqrtf(t0 * t0 + t1 * t1), 1e-12f);
            wav *= (xs > 0.0f ? t0 : t1) / nrm;
        }
        buf ^= 1;
    }

    if (leader) out[n0 + nl] = wav;
}

extern "C" void kernel_launch(void* const* d_in, const int* in_sizes, int n_in,
                              void* d_out, int out_size) {
    const float* x  = (const float*)d_in[0];   // [8192,64]
    const float* W1 = (const float*)d_in[1];   // [64,4096]
    const float* b1 = (const float*)d_in[2];   // [4096]
    const float* W2 = (const float*)d_in[3];   // [4096,2]
    const float* b2 = (const float*)d_in[4];   // [2]
    float* out = (float*)d_out;                // [8192]

    const int smem_bytes =
        (4 * CH + B_SAMP * D_SITES) * (int)sizeof(float) + 32 * (int)sizeof(float2);

    cudaFuncSetAttribute(qnade_kernel,
                         cudaFuncAttributeMaxDynamicSharedMemorySize, smem_bytes);

    qnade_kernel<<<N_SAMP / B_SAMP, THREADS, smem_bytes>>>(x, W1, b1, W2, b2, out);
}